// round 9
// baseline (speedup 1.0000x reference)
#include <cuda_runtime.h>
#include <cuda_bf16.h>
#include <math.h>

#define DEV_DIM 192
#define PE_DIM  64
#define EMB     256
#define XDIM    256          // K of GEMM1
#define OUTW    512
#define MAXM    262144
#define MAXB    1024

// ===================== scratch (no allocations allowed) =====================
__device__ float g_sums[MAXB * EMB];
__device__ float g_maxs[MAXB * EMB];
__device__ float g_agg [MAXB * EMB];
__device__ float g_pos [MAXM];
__device__ int   g_bidx[MAXM];
__device__ __nv_bfloat16 g_wt_hi[EMB * XDIM];   // W1^T hi  [n][k]
__device__ __nv_bfloat16 g_wt_lo[EMB * XDIM];   // W1^T lo  [n][k]

// ===================== helpers =====================
__device__ __forceinline__ unsigned smem_u32(const void* p) {
    unsigned a;
    asm("{ .reg .u64 t; cvta.to.shared.u64 t, %1; cvt.u32.u64 %0, t; }" : "=r"(a) : "l"(p));
    return a;
}
__device__ __forceinline__ void cp_async16(unsigned dst, const void* src) {
    asm volatile("cp.async.cg.shared.global [%0], [%1], 16;" :: "r"(dst), "l"(src));
}
#define CP_ASYNC_COMMIT()   asm volatile("cp.async.commit_group;" ::: "memory")
#define CP_ASYNC_WAIT_ALL() asm volatile("cp.async.wait_group 0;" ::: "memory")
#define CP_ASYNC_WAIT_1()   asm volatile("cp.async.wait_group 1;" ::: "memory")

#define LDSM_X4(r0, r1, r2, r3, addr)                                          \
    asm volatile("ldmatrix.sync.aligned.m8n8.x4.shared.b16 {%0,%1,%2,%3}, [%4];" \
        : "=r"(r0), "=r"(r1), "=r"(r2), "=r"(r3) : "r"(addr))

__device__ __forceinline__ void mma_bf16(float* d, const unsigned* a, const unsigned* b) {
    asm volatile(
        "mma.sync.aligned.m16n8k16.row.col.f32.bf16.bf16.f32 "
        "{%0,%1,%2,%3}, {%4,%5,%6,%7}, {%8,%9}, {%0,%1,%2,%3};"
        : "+f"(d[0]), "+f"(d[1]), "+f"(d[2]), "+f"(d[3])
        : "r"(a[0]), "r"(a[1]), "r"(a[2]), "r"(a[3]), "r"(b[0]), "r"(b[1]));
}

__device__ __forceinline__ void atomicMaxF(float* addr, float v) {
    if (v >= 0.0f) atomicMax((int*)addr, __float_as_int(v));
    else           atomicMin((unsigned int*)addr, __float_as_uint(v));
}
__device__ __forceinline__ unsigned packbf2(float v0, float v1, float* r0, float* r1) {
    __nv_bfloat16 h0 = __float2bfloat16_rn(v0);
    __nv_bfloat16 h1 = __float2bfloat16_rn(v1);
    *r0 = v0 - __bfloat162float(h0);
    *r1 = v1 - __bfloat162float(h1);
    return ((unsigned)__bfloat16_as_ushort(h1) << 16) | (unsigned)__bfloat16_as_ushort(h0);
}
__device__ __forceinline__ unsigned packbf2_only(float v0, float v1) {
    return ((unsigned)__bfloat16_as_ushort(__float2bfloat16_rn(v1)) << 16)
         | (unsigned)__bfloat16_as_ushort(__float2bfloat16_rn(v0));
}

// ===================== kernel 0: init segment accumulators =====================
__global__ void k_init(int B) {
    int i = blockIdx.x * blockDim.x + threadIdx.x;
    if (i < B * EMB) {
        g_sums[i] = 0.0f;
        ((unsigned int*)g_maxs)[i] = 0xFF800000u;   // -inf
    }
}

// ===================== kernel 1: batch_index + 1-based position =====================
__global__ void k_bidx(const int* __restrict__ si, int M, int B) {
    int j = blockIdx.x * blockDim.x + threadIdx.x;
    if (j >= M) return;
    int lo = 1, hi = B + 1;
    while (lo < hi) {
        int mid = (lo + hi) >> 1;
        if (__ldg(si + mid) <= j) lo = mid + 1; else hi = mid;
    }
    int seg = lo - 1;
    g_bidx[j] = seg;
    g_pos[j]  = (float)(j - __ldg(si + seg) + 1);
}

// ===================== kernel 1b: W1 -> transposed bf16 hi/lo =====================
__global__ void k_prep(const float* __restrict__ W1) {
    int n = blockIdx.x;           // output col 0..255
    int k = threadIdx.x;          // k 0..255
    float w = __ldg(W1 + (size_t)k * EMB + n);
    __nv_bfloat16 h = __float2bfloat16_rn(w);
    g_wt_hi[n * XDIM + k] = h;
    g_wt_lo[n * XDIM + k] = __float2bfloat16_rn(w - __bfloat162float(h));
}

// ===================== kernel 2: bf16x3 HMMA GEMM1, A resident in smem =====================
// CTA: 128 rows x 256 cols (FULL N), 256 threads (8 warps, warp tile 64x64).
// A (hi+lo, full K=256) computed once into smem; B streamed in 8 chunks of 32 k,
// 2-stage cp.async ring.
#define KC        32
#define NCHK      8
#define PA_B      40                    // B smem pitch in bf16 (80 B)
#define B_MAT     20480                 // 256 * 80 B per matrix per stage
#define B_STAGE   40960                 // hi + lo
#define B_TILE    1280                  // 16 * 80 B
#define PA_AB     528                   // A row pitch in BYTES (264 bf16); 528%128=16 -> ldsm conflict-free
#define A_MAT     67584                 // 128 * 528
#define A_TILE_R  8448                  // 16 * 528
#define OFF_BIAS  0                     // 256 f32
#define OFF_INVF  1024                  // 32 f32
#define OFF_A     1280                  // AH | AL  (2 * 67584 = 135168)
#define OFF_B     136448                // 2 stages * 40960 = 81920
#define SMEM_G1   218368

__device__ __forceinline__ void stage_B(unsigned sb, int ck, int buf) {
    int tid = threadIdx.x;
    unsigned bh = sb + OFF_B + buf * B_STAGE;
    unsigned bl = bh + B_MAT;
    const char* srcH = (const char*)(g_wt_hi) + ck * (KC * 2);
    const char* srcL = (const char*)(g_wt_lo) + ck * (KC * 2);
    // per matrix: 256 n-rows * 4 x 16B segments = 1024 txns; 256 threads -> 4 each
#pragma unroll
    for (int t = 0; t < 4; t++) {
        int i = tid + t * 256;
        int n = i >> 2, s = i & 3;
        unsigned d = (unsigned)(n * (PA_B * 2) + s * 16);
        cp_async16(bh + d, srcH + (size_t)n * (XDIM * 2) + s * 16);
        cp_async16(bl + d, srcL + (size_t)n * (XDIM * 2) + s * 16);
    }
}

__device__ __forceinline__ void load_A_vals(const float* __restrict__ states,
                                            float pos, const float* sinvf,
                                            int grow, int valid, int ck, float* v) {
    int kq = (threadIdx.x & 1) * 16;
    int kbase = ck * KC + kq;
    if (ck < 6) {                       // pure states
        if (valid) {
            const float4* p = (const float4*)(states + (size_t)grow * DEV_DIM + kbase);
#pragma unroll
            for (int q = 0; q < 4; q++) {
                float4 x = __ldg(p + q);
                v[q * 4 + 0] = x.x; v[q * 4 + 1] = x.y;
                v[q * 4 + 2] = x.z; v[q * 4 + 3] = x.w;
            }
        } else {
#pragma unroll
            for (int e = 0; e < 16; e++) v[e] = 0.0f;
        }
    } else {                            // pure PE (k 192..255)
        int c0 = kbase - DEV_DIM;       // 0/16/32/48
#pragma unroll
        for (int f = 0; f < 8; f++) {
            float ang = pos * sinvf[(c0 >> 1) + f];
            float kq2 = rintf(ang * 0.15915494309189535f);
            float rr = fmaf(kq2, -6.28125f, ang);
            rr = fmaf(kq2, -1.9353071795864769e-3f, rr);
            float s, c;
            __sincosf(rr, &s, &c);
            v[2 * f] = s; v[2 * f + 1] = c;
        }
    }
}

__global__ __launch_bounds__(256, 1) void k_gemm1_mma(
    const float* __restrict__ states, const float* __restrict__ b1,
    float* __restrict__ out, int M)
{
    extern __shared__ char smem[];
    const unsigned sb = smem_u32(smem);
    const int tid  = threadIdx.x;
    const int wid  = tid >> 5;
    const int lane = tid & 31;
    const int g    = lane >> 2;
    const int tg   = lane & 3;
    const int wm   = wid >> 2;       // 0..1 (64 rows)
    const int wn   = wid & 3;        // 0..3 (64 cols)
    const int row0 = blockIdx.x * 128;

    float* sbias = (float*)(smem + OFF_BIAS);
    float* sinvf = (float*)(smem + OFF_INVF);

    if (tid < 256) sbias[tid] = __ldg(b1 + tid);
    if (tid < 32) {
        float lg = logf(10000.0f);
        sinvf[tid] = expf(-(lg * ((2.0f * (float)tid) / (float)PE_DIM)));
    }

    // ---- prologue: kick off B chunks 0 and 1 ----
    stage_B(sb, 0, 0);
    CP_ASYNC_COMMIT();
    stage_B(sb, 1, 1);
    CP_ASYNC_COMMIT();

    __syncthreads();   // sinvf visible

    // ---- build resident A (hi/lo, full K) in smem ----
    {
        const int arow  = tid >> 1;
        const int kq    = (tid & 1) * 16;
        const int grow  = row0 + arow;
        const int valid = (grow < M);
        const float pos = valid ? __ldg(&g_pos[grow]) : 1.0f;
#pragma unroll 1
        for (int ck = 0; ck < NCHK; ck++) {
            float v[16];
            load_A_vals(states, pos, sinvf, grow, valid, ck, v);
            unsigned hi[8], lo[8];
#pragma unroll
            for (int q = 0; q < 8; q++) {
                float r0, r1;
                hi[q] = packbf2(v[2 * q], v[2 * q + 1], &r0, &r1);
                lo[q] = packbf2_only(r0, r1);
            }
            char* ah = smem + OFF_A + arow * PA_AB + (ck * KC + kq) * 2;
            char* al = ah + A_MAT;
            ((uint4*)ah)[0] = make_uint4(hi[0], hi[1], hi[2], hi[3]);
            ((uint4*)ah)[1] = make_uint4(hi[4], hi[5], hi[6], hi[7]);
            ((uint4*)al)[0] = make_uint4(lo[0], lo[1], lo[2], lo[3]);
            ((uint4*)al)[1] = make_uint4(lo[4], lo[5], lo[6], lo[7]);
        }
    }
    __syncthreads();   // resident A ready for all warps

    // ldmatrix per-lane base offsets
    const int g4 = lane >> 3;           // 0..3
    const int lr = lane & 7;
    const unsigned a_off = sb + OFF_A
        + (unsigned)((wm * 64 + (g4 & 1) * 8 + lr) * PA_AB) + (g4 >> 1) * 16;
    const unsigned b_off = (unsigned)((wn * 64 + (g4 >> 1) * 8 + lr) * (PA_B * 2)) + (g4 & 1) * 16;

    float acc[4][8][4];
#pragma unroll
    for (int i = 0; i < 4; i++)
#pragma unroll
        for (int j = 0; j < 8; j++)
#pragma unroll
            for (int e = 0; e < 4; e++) acc[i][j][e] = 0.0f;

#pragma unroll 1
    for (int c = 0; c < NCHK; c++) {
        const int buf = c & 1;
        if (c < NCHK - 1) CP_ASYNC_WAIT_1(); else CP_ASYNC_WAIT_ALL();
        __syncthreads();

        const unsigned sBH = sb + OFF_B + buf * B_STAGE;
        const unsigned sBL = sBH + B_MAT;
        const unsigned akc = (unsigned)(c * (KC * 2));   // byte offset into resident A

#pragma unroll
        for (int ks = 0; ks < 2; ks++) {
            const unsigned ka = akc + ks * 32;           // A k-offset (bytes)
            const unsigned kb = ks * 32;                 // B k-offset (bytes)
            unsigned ah[4][4], al[4][4];
#pragma unroll
            for (int i = 0; i < 4; i++) {
                LDSM_X4(ah[i][0], ah[i][1], ah[i][2], ah[i][3],
                        a_off + i * A_TILE_R + ka);
                LDSM_X4(al[i][0], al[i][1], al[i][2], al[i][3],
                        a_off + A_MAT + i * A_TILE_R + ka);
            }
#pragma unroll
            for (int jj = 0; jj < 4; jj++) {
                unsigned bh[2][2], bl[2][2];
                LDSM_X4(bh[0][0], bh[0][1], bh[1][0], bh[1][1],
                        sBH + b_off + jj * B_TILE + kb);
                LDSM_X4(bl[0][0], bl[0][1], bl[1][0], bl[1][1],
                        sBL + b_off + jj * B_TILE + kb);
#pragma unroll
                for (int i = 0; i < 4; i++) {
#pragma unroll
                    for (int p = 0; p < 2; p++) {
                        mma_bf16(acc[i][2 * jj + p], ah[i], bh[p]);
                        mma_bf16(acc[i][2 * jj + p], ah[i], bl[p]);
                        mma_bf16(acc[i][2 * jj + p], al[i], bh[p]);
                    }
                }
            }
        }

        __syncthreads();                 // all warps done reading buf
        if (c + 2 < NCHK) {
            stage_B(sb, c + 2, buf);
            CP_ASYNC_COMMIT();
        }
    }

    // ---- epilogue: bias + LeakyReLU, store out[:, 0:256) ----
#pragma unroll
    for (int i = 0; i < 4; i++) {
        int ra = row0 + wm * 64 + i * 16 + g;
#pragma unroll
        for (int h = 0; h < 2; h++) {
            int row = ra + h * 8;
            if (row < M) {
                float* op = out + (size_t)row * OUTW + wn * 64;
#pragma unroll
                for (int j = 0; j < 8; j++) {
                    int ccol = j * 8 + tg * 2;
                    float x0 = acc[i][j][h * 2 + 0] + sbias[wn * 64 + ccol];
                    float x1 = acc[i][j][h * 2 + 1] + sbias[wn * 64 + ccol + 1];
                    x0 = (x0 >= 0.0f) ? x0 : 0.01f * x0;
                    x1 = (x1 >= 0.0f) ? x1 : 0.01f * x1;
                    *(float2*)(op + ccol) = make_float2(x0, x1);
                }
            }
        }
    }
}

// ===================== kernel 3: ragged segment sum + max (prefetched) =====================
__global__ __launch_bounds__(256) void k_segred(const float* __restrict__ out, int M) {
    __shared__ int sseg[256];
    int c = threadIdx.x;
    int row0 = blockIdx.x * 256;
    int rows = min(256, M - row0);
    sseg[c] = __ldg(&g_bidx[row0 + min(c, rows - 1)]);
    __syncthreads();
    const float* p = out + (size_t)row0 * OUTW + c;
    float v[8];
#pragma unroll
    for (int i = 0; i < 8; i++)
        v[i] = (i < rows) ? __ldg(p + (size_t)i * OUTW) : 0.0f;
    float sum = 0.0f, mx = __int_as_float(0xFF800000);
    int cur = sseg[0];
#pragma unroll 8
    for (int r = 0; r < 256; r++) {
        if (r >= rows) break;
        float val = v[r & 7];
        if (r + 8 < rows) v[r & 7] = __ldg(p + (size_t)(r + 8) * OUTW);
        int seg = sseg[r];
        if (seg != cur) {
            atomicAdd(&g_sums[cur * EMB + c], sum);
            atomicMaxF(&g_maxs[cur * EMB + c], mx);
            sum = 0.0f; mx = __int_as_float(0xFF800000); cur = seg;
        }
        sum += val;
        mx = fmaxf(mx, val);
    }
    atomicAdd(&g_sums[cur * EMB + c], sum);
    atomicMaxF(&g_maxs[cur * EMB + c], mx);
}

// ===================== kernel 4: agg = leaky(concat(mean,max) @ W2 + b2) =====================
__global__ __launch_bounds__(256) void k_mlp(const int* __restrict__ si,
                                             const float* __restrict__ W2,
                                             const float* __restrict__ b2) {
    __shared__ float vec[2 * EMB];
    __shared__ float par[4][EMB];
    int s = blockIdx.x, t = threadIdx.x;
    int cnt = __ldg(si + s + 1) - __ldg(si + s);
    float inv = (cnt > 0) ? (1.0f / (float)cnt) : 1.0f;
    vec[t]       = g_sums[s * EMB + t] * inv;
    vec[EMB + t] = (cnt > 0) ? g_maxs[s * EMB + t] : 0.0f;
    __syncthreads();
    int tq = t >> 6;
    int tc = (t & 63) * 4;
    float a0 = 0.f, a1 = 0.f, a2 = 0.f, a3 = 0.f;
#pragma unroll 4
    for (int k = tq * 128; k < tq * 128 + 128; k++) {
        float vk = vec[k];
        float4 w = __ldg((const float4*)(W2 + (size_t)k * EMB + tc));
        a0 = fmaf(vk, w.x, a0); a1 = fmaf(vk, w.y, a1);
        a2 = fmaf(vk, w.z, a2); a3 = fmaf(vk, w.w, a3);
    }
    par[tq][tc] = a0; par[tq][tc + 1] = a1; par[tq][tc + 2] = a2; par[tq][tc + 3] = a3;
    __syncthreads();
    if (tq == 0) {
#pragma unroll
        for (int e = 0; e < 4; e++) {
            int cc = tc + e;
            float acc = par[0][cc] + par[1][cc] + par[2][cc] + par[3][cc] + __ldg(b2 + cc);
            acc = (acc >= 0.0f) ? acc : 0.01f * acc;
            g_agg[s * EMB + cc] = acc;
        }
    }
}

// ===================== kernel 5: broadcast agg into out[:, 256:512] =====================
__global__ __launch_bounds__(256) void k_bcast(float* __restrict__ out, int M) {
    int idx = blockIdx.x * blockDim.x + threadIdx.x;
    int row = idx >> 6;
    int q   = idx & 63;
    if (row >= M) return;
    int seg = __ldg(&g_bidx[row]);
    float4 v = __ldg((const float4*)(g_agg + (size_t)seg * EMB) + q);
    *((float4*)(out + (size_t)row * OUTW + EMB) + q) = v;
}

// ===================== kernel 6 (optional): second tuple output (batch_index) =====================
__global__ void k_tail(float* __restrict__ out, size_t off, int M) {
    int j = blockIdx.x * blockDim.x + threadIdx.x;
    if (j < M) out[off + j] = (float)g_bidx[j];
}

// ===================== launch =====================
extern "C" void kernel_launch(void* const* d_in, const int* in_sizes, int n_in,
                              void* d_out, int out_size) {
    const float* states = (const float*)d_in[0];
    const int*   si     = (const int*)  d_in[1];
    const float* W1     = (const float*)d_in[2];
    const float* b1     = (const float*)d_in[3];
    const float* W2     = (const float*)d_in[4];
    const float* b2     = (const float*)d_in[5];
    float* out = (float*)d_out;

    int M = in_sizes[0] / DEV_DIM;
    int B = in_sizes[1] - 1;
    if (M > MAXM) M = MAXM;
    if (B > MAXB) B = MAXB;

    cudaFuncSetAttribute(k_gemm1_mma, cudaFuncAttributeMaxDynamicSharedMemorySize, SMEM_G1);

    k_init     <<<(B * EMB + 255) / 256, 256>>>(B);
    k_bidx     <<<(M + 255) / 256, 256>>>(si, M, B);
    k_prep     <<<EMB, XDIM>>>(W1);
    k_gemm1_mma<<<(M + 127) / 128, 256, SMEM_G1>>>(states, b1, out, M);
    k_segred   <<<(M + 255) / 256, 256>>>(out, M);
    k_mlp      <<<B, 256>>>(si, W2, b2);
    k_bcast    <<<(M * 64 + 255) / 256, 256>>>(out, M);

    long long need = (long long)M * OUTW + (long long)M;
    if ((long long)out_size >= need)
        k_tail<<<(M + 255) / 256, 256>>>(out, (size_t)M * OUTW, M);
}

// round 10
// speedup vs baseline: 1.0141x; 1.0141x over previous
#include <cuda_runtime.h>
#include <cuda_bf16.h>
#include <math.h>

#define DEV_DIM 192
#define PE_DIM  64
#define EMB     256
#define XDIM    256          // K of GEMM1
#define OUTW    512
#define MAXM    262144
#define MAXB    1024

// ===================== scratch (no allocations allowed) =====================
__device__ float g_sums[MAXB * EMB];
__device__ float g_maxs[MAXB * EMB];
__device__ float g_agg [MAXB * EMB];
__device__ float g_pos [MAXM];
__device__ int   g_bidx[MAXM];
__device__ __nv_bfloat16 g_wt_hi[EMB * XDIM];   // W1^T hi  [n][k]
__device__ __nv_bfloat16 g_wt_lo[EMB * XDIM];   // W1^T lo  [n][k]

// ===================== helpers =====================
__device__ __forceinline__ unsigned smem_u32(const void* p) {
    unsigned a;
    asm("{ .reg .u64 t; cvta.to.shared.u64 t, %1; cvt.u32.u64 %0, t; }" : "=r"(a) : "l"(p));
    return a;
}
__device__ __forceinline__ void cp_async16(unsigned dst, const void* src) {
    asm volatile("cp.async.cg.shared.global [%0], [%1], 16;" :: "r"(dst), "l"(src));
}
#define CP_ASYNC_COMMIT()   asm volatile("cp.async.commit_group;" ::: "memory")
#define CP_ASYNC_WAIT_ALL() asm volatile("cp.async.wait_group 0;" ::: "memory")

#define LDSM_X4(r0, r1, r2, r3, addr)                                          \
    asm volatile("ldmatrix.sync.aligned.m8n8.x4.shared.b16 {%0,%1,%2,%3}, [%4];" \
        : "=r"(r0), "=r"(r1), "=r"(r2), "=r"(r3) : "r"(addr))

__device__ __forceinline__ void mma_bf16(float* d, const unsigned* a, const unsigned* b) {
    asm volatile(
        "mma.sync.aligned.m16n8k16.row.col.f32.bf16.bf16.f32 "
        "{%0,%1,%2,%3}, {%4,%5,%6,%7}, {%8,%9}, {%0,%1,%2,%3};"
        : "+f"(d[0]), "+f"(d[1]), "+f"(d[2]), "+f"(d[3])
        : "r"(a[0]), "r"(a[1]), "r"(a[2]), "r"(a[3]), "r"(b[0]), "r"(b[1]));
}

__device__ __forceinline__ void atomicMaxF(float* addr, float v) {
    if (v >= 0.0f) atomicMax((int*)addr, __float_as_int(v));
    else           atomicMin((unsigned int*)addr, __float_as_uint(v));
}
__device__ __forceinline__ unsigned packbf2(float v0, float v1, float* r0, float* r1) {
    __nv_bfloat16 h0 = __float2bfloat16_rn(v0);
    __nv_bfloat16 h1 = __float2bfloat16_rn(v1);
    *r0 = v0 - __bfloat162float(h0);
    *r1 = v1 - __bfloat162float(h1);
    return ((unsigned)__bfloat16_as_ushort(h1) << 16) | (unsigned)__bfloat16_as_ushort(h0);
}
__device__ __forceinline__ unsigned packbf2_only(float v0, float v1) {
    return ((unsigned)__bfloat16_as_ushort(__float2bfloat16_rn(v1)) << 16)
         | (unsigned)__bfloat16_as_ushort(__float2bfloat16_rn(v0));
}

// ===================== kernel 0: init segment accumulators =====================
__global__ void k_init(int B) {
    int i = blockIdx.x * blockDim.x + threadIdx.x;
    if (i < B * EMB) {
        g_sums[i] = 0.0f;
        ((unsigned int*)g_maxs)[i] = 0xFF800000u;   // -inf
    }
}

// ===================== kernel 1: batch_index + 1-based position =====================
__global__ void k_bidx(const int* __restrict__ si, int M, int B) {
    int j = blockIdx.x * blockDim.x + threadIdx.x;
    if (j >= M) return;
    int lo = 1, hi = B + 1;
    while (lo < hi) {
        int mid = (lo + hi) >> 1;
        if (__ldg(si + mid) <= j) lo = mid + 1; else hi = mid;
    }
    int seg = lo - 1;
    g_bidx[j] = seg;
    g_pos[j]  = (float)(j - __ldg(si + seg) + 1);
}

// ===================== kernel 1b: W1 -> transposed bf16 hi/lo =====================
__global__ void k_prep(const float* __restrict__ W1) {
    int n = blockIdx.x;           // output col 0..255
    int k = threadIdx.x;          // k 0..255
    float w = __ldg(W1 + (size_t)k * EMB + n);
    __nv_bfloat16 h = __float2bfloat16_rn(w);
    g_wt_hi[n * XDIM + k] = h;
    g_wt_lo[n * XDIM + k] = __float2bfloat16_rn(w - __bfloat162float(h));
}

// ===================== kernel 2: bf16x3 HMMA GEMM1 + fused segment reduce =====================
// CTA: 128 rows x 256 cols (FULL N), 256 threads (8 warps, warp tile 64x64).
// K=256 in 8 chunks of 32, double buffered (A staged per chunk, as in round 7).
// After MMAs: h dual-written to global + smem, then in-CTA ragged segment
// sum/max scan with atomic merge (replaces the separate k_segred kernel).
#define KC       32
#define NCHK     8
#define PA       40                     // smem pitch in bf16 (80 B)
#define A_BUF    10240                  // 128 * 80 B per matrix
#define B_BUF    20480                  // 256 * 80 B per matrix
#define A_TILE   1280                   // 16 * 80 B (one 16-row tile)
#define OFF_BIAS 0                      // 256 f32
#define OFF_INVF 1024                   // 32 f32
#define OFF_A    1280                   // [buf][AH | AL]
#define OFF_B    42240                  // [buf][BH | BL]
// h tile overlaps the dead A+B regions after the final mainloop sync
#define OFF_H    1280
#define PITCH_H  258                    // f32 pitch (1032 B): conflict-free scan + writes
#define OFF_SB   133376                 // 128 ints (bidx cache), after h
#define SMEM_G1  133888

__device__ __forceinline__ void stage_B(unsigned sb, int ck, int buf) {
    int tid = threadIdx.x;
    unsigned bh = sb + OFF_B + buf * (2 * B_BUF);
    unsigned bl = bh + B_BUF;
    const char* srcH = (const char*)(g_wt_hi) + ck * (KC * 2);
    const char* srcL = (const char*)(g_wt_lo) + ck * (KC * 2);
#pragma unroll
    for (int t = 0; t < 4; t++) {
        int i = tid + t * 256;
        int n = i >> 2, s = i & 3;
        unsigned d = (unsigned)(n * (PA * 2) + s * 16);
        cp_async16(bh + d, srcH + (size_t)n * (XDIM * 2) + s * 16);
        cp_async16(bl + d, srcL + (size_t)n * (XDIM * 2) + s * 16);
    }
}

__device__ __forceinline__ void load_A_vals(const float* __restrict__ states,
                                            float pos, const float* sinvf,
                                            int grow, int valid, int ck, float* v) {
    int kq = (threadIdx.x & 1) * 16;
    int kbase = ck * KC + kq;
    if (ck < 6) {                       // pure states
        if (valid) {
            const float4* p = (const float4*)(states + (size_t)grow * DEV_DIM + kbase);
#pragma unroll
            for (int q = 0; q < 4; q++) {
                float4 x = __ldg(p + q);
                v[q * 4 + 0] = x.x; v[q * 4 + 1] = x.y;
                v[q * 4 + 2] = x.z; v[q * 4 + 3] = x.w;
            }
        } else {
#pragma unroll
            for (int e = 0; e < 16; e++) v[e] = 0.0f;
        }
    } else {                            // pure PE (k 192..255)
        int c0 = kbase - DEV_DIM;       // 0/16/32/48
#pragma unroll
        for (int f = 0; f < 8; f++) {
            float ang = pos * sinvf[(c0 >> 1) + f];
            float kq2 = rintf(ang * 0.15915494309189535f);
            float rr = fmaf(kq2, -6.28125f, ang);
            rr = fmaf(kq2, -1.9353071795864769e-3f, rr);
            float s, c;
            __sincosf(rr, &s, &c);
            v[2 * f] = s; v[2 * f + 1] = c;
        }
    }
}

__device__ __forceinline__ void store_A(char* smem, int buf, const float* v) {
    int arow = threadIdx.x >> 1;
    int kq   = (threadIdx.x & 1) * 16;
    unsigned hi[8], lo[8];
#pragma unroll
    for (int q = 0; q < 8; q++) {
        float r0, r1;
        hi[q] = packbf2(v[2 * q], v[2 * q + 1], &r0, &r1);
        lo[q] = packbf2_only(r0, r1);
    }
    char* ah = smem + OFF_A + buf * (2 * A_BUF) + arow * (PA * 2) + kq * 2;
    char* al = ah + A_BUF;
    ((uint4*)ah)[0] = make_uint4(hi[0], hi[1], hi[2], hi[3]);
    ((uint4*)ah)[1] = make_uint4(hi[4], hi[5], hi[6], hi[7]);
    ((uint4*)al)[0] = make_uint4(lo[0], lo[1], lo[2], lo[3]);
    ((uint4*)al)[1] = make_uint4(lo[4], lo[5], lo[6], lo[7]);
}

__global__ __launch_bounds__(256, 1) void k_gemm1_mma(
    const float* __restrict__ states, const float* __restrict__ b1,
    float* __restrict__ out, int M)
{
    extern __shared__ char smem[];
    const unsigned sb = smem_u32(smem);
    const int tid  = threadIdx.x;
    const int wid  = tid >> 5;
    const int lane = tid & 31;
    const int g    = lane >> 2;
    const int tg   = lane & 3;
    const int wm   = wid >> 2;       // 0..1 (64 rows)
    const int wn   = wid & 3;        // 0..3 (64 cols)
    const int row0 = blockIdx.x * 128;

    float* sbias = (float*)(smem + OFF_BIAS);
    float* sinvf = (float*)(smem + OFF_INVF);

    if (tid < 256) sbias[tid] = __ldg(b1 + tid);
    if (tid < 32) {
        float lg = logf(10000.0f);
        sinvf[tid] = expf(-(lg * ((2.0f * (float)tid) / (float)PE_DIM)));
    }
    __syncthreads();

    const int arow  = tid >> 1;
    const int grow  = row0 + arow;
    const int valid = (grow < M);
    const float pos = valid ? __ldg(&g_pos[grow]) : 1.0f;

    // ldmatrix per-lane base offsets
    const int g4 = lane >> 3;           // 0..3
    const int lr = lane & 7;
    const unsigned a_off = (unsigned)((wm * 64 + (g4 & 1) * 8 + lr) * (PA * 2)) + (g4 >> 1) * 16;
    const unsigned b_off = (unsigned)((wn * 64 + (g4 >> 1) * 8 + lr) * (PA * 2)) + (g4 & 1) * 16;

    // ---- prologue: chunk 0 ----
    stage_B(sb, 0, 0);
    CP_ASYNC_COMMIT();
    {
        float v[16];
        load_A_vals(states, pos, sinvf, grow, valid, 0, v);
        store_A(smem, 0, v);
    }
    CP_ASYNC_WAIT_ALL();
    __syncthreads();

    float acc[4][8][4];
#pragma unroll
    for (int i = 0; i < 4; i++)
#pragma unroll
        for (int j = 0; j < 8; j++)
#pragma unroll
            for (int e = 0; e < 4; e++) acc[i][j][e] = 0.0f;

#pragma unroll 1
    for (int c = 0; c < NCHK; c++) {
        const int buf = c & 1;
        float vnext[16];
        const bool more = (c < NCHK - 1);
        if (more) {
            stage_B(sb, c + 1, buf ^ 1);
            CP_ASYNC_COMMIT();
            load_A_vals(states, pos, sinvf, grow, valid, c + 1, vnext);
        }

        const unsigned sAH = sb + OFF_A + buf * (2 * A_BUF);
        const unsigned sAL = sAH + A_BUF;
        const unsigned sBH = sb + OFF_B + buf * (2 * B_BUF);
        const unsigned sBL = sBH + B_BUF;

#pragma unroll
        for (int ks = 0; ks < 2; ks++) {
            const unsigned kb = ks * 32;            // 16 k * 2 B
            unsigned ah[4][4], al[4][4];
#pragma unroll
            for (int i = 0; i < 4; i++) {
                LDSM_X4(ah[i][0], ah[i][1], ah[i][2], ah[i][3],
                        sAH + a_off + i * A_TILE + kb);
                LDSM_X4(al[i][0], al[i][1], al[i][2], al[i][3],
                        sAL + a_off + i * A_TILE + kb);
            }
#pragma unroll
            for (int jj = 0; jj < 4; jj++) {
                unsigned bh[2][2], bl[2][2];
                LDSM_X4(bh[0][0], bh[0][1], bh[1][0], bh[1][1],
                        sBH + b_off + jj * A_TILE + kb);
                LDSM_X4(bl[0][0], bl[0][1], bl[1][0], bl[1][1],
                        sBL + b_off + jj * A_TILE + kb);
#pragma unroll
                for (int i = 0; i < 4; i++) {
#pragma unroll
                    for (int p = 0; p < 2; p++) {
                        mma_bf16(acc[i][2 * jj + p], ah[i], bh[p]);
                        mma_bf16(acc[i][2 * jj + p], ah[i], bl[p]);
                        mma_bf16(acc[i][2 * jj + p], al[i], bh[p]);
                    }
                }
            }
        }

        if (more) {
            store_A(smem, buf ^ 1, vnext);
            CP_ASYNC_WAIT_ALL();
            __syncthreads();
        }
    }
    __syncthreads();   // all MMAs done; A/B smem is now dead -> reuse for h

    // ---- epilogue: bias + LeakyReLU; dual-write h to global and smem ----
    float* hs   = (float*)(smem + OFF_H);
    int*   sbid = (int*)(smem + OFF_SB);
    const int rows = min(128, M - row0);
    if (tid < 128) sbid[tid] = __ldg(&g_bidx[row0 + min(tid, rows - 1)]);

#pragma unroll
    for (int i = 0; i < 4; i++) {
        int rl = wm * 64 + i * 16 + g;
#pragma unroll
        for (int h = 0; h < 2; h++) {
            int rloc = rl + h * 8;
            int row  = row0 + rloc;
            if (row < M) {
                float* op = out + (size_t)row * OUTW + wn * 64;
                float* hp = hs + rloc * PITCH_H + wn * 64;
#pragma unroll
                for (int j = 0; j < 8; j++) {
                    int ccol = j * 8 + tg * 2;
                    float x0 = acc[i][j][h * 2 + 0] + sbias[wn * 64 + ccol];
                    float x1 = acc[i][j][h * 2 + 1] + sbias[wn * 64 + ccol + 1];
                    x0 = (x0 >= 0.0f) ? x0 : 0.01f * x0;
                    x1 = (x1 >= 0.0f) ? x1 : 0.01f * x1;
                    float2 xv = make_float2(x0, x1);
                    *(float2*)(op + ccol) = xv;
                    *(float2*)(hp + ccol) = xv;
                }
            }
        }
    }
    __syncthreads();   // h + sbid visible

    // ---- fused ragged segment sum/max over this CTA's 128 rows ----
    {
        const int c = tid;              // column 0..255
        float sum = 0.0f, mx = __int_as_float(0xFF800000);
        int cur = sbid[0];
#pragma unroll 4
        for (int r = 0; r < 128; r++) {
            if (r >= rows) break;
            float val = hs[r * PITCH_H + c];
            int seg = sbid[r];
            if (seg != cur) {
                atomicAdd(&g_sums[cur * EMB + c], sum);
                atomicMaxF(&g_maxs[cur * EMB + c], mx);
                sum = 0.0f; mx = __int_as_float(0xFF800000); cur = seg;
            }
            sum += val;
            mx = fmaxf(mx, val);
        }
        atomicAdd(&g_sums[cur * EMB + c], sum);
        atomicMaxF(&g_maxs[cur * EMB + c], mx);
    }
}

// ===================== kernel 4: agg = leaky(concat(mean,max) @ W2 + b2) =====================
__global__ __launch_bounds__(256) void k_mlp(const int* __restrict__ si,
                                             const float* __restrict__ W2,
                                             const float* __restrict__ b2) {
    __shared__ float vec[2 * EMB];
    __shared__ float par[4][EMB];
    int s = blockIdx.x, t = threadIdx.x;
    int cnt = __ldg(si + s + 1) - __ldg(si + s);
    float inv = (cnt > 0) ? (1.0f / (float)cnt) : 1.0f;
    vec[t]       = g_sums[s * EMB + t] * inv;
    vec[EMB + t] = (cnt > 0) ? g_maxs[s * EMB + t] : 0.0f;
    __syncthreads();
    int tq = t >> 6;
    int tc = (t & 63) * 4;
    float a0 = 0.f, a1 = 0.f, a2 = 0.f, a3 = 0.f;
#pragma unroll 4
    for (int k = tq * 128; k < tq * 128 + 128; k++) {
        float vk = vec[k];
        float4 w = __ldg((const float4*)(W2 + (size_t)k * EMB + tc));
        a0 = fmaf(vk, w.x, a0); a1 = fmaf(vk, w.y, a1);
        a2 = fmaf(vk, w.z, a2); a3 = fmaf(vk, w.w, a3);
    }
    par[tq][tc] = a0; par[tq][tc + 1] = a1; par[tq][tc + 2] = a2; par[tq][tc + 3] = a3;
    __syncthreads();
    if (tq == 0) {
#pragma unroll
        for (int e = 0; e < 4; e++) {
            int cc = tc + e;
            float acc = par[0][cc] + par[1][cc] + par[2][cc] + par[3][cc] + __ldg(b2 + cc);
            acc = (acc >= 0.0f) ? acc : 0.01f * acc;
            g_agg[s * EMB + cc] = acc;
        }
    }
}

// ===================== kernel 5: broadcast agg into out[:, 256:512] =====================
__global__ __launch_bounds__(256) void k_bcast(float* __restrict__ out, int M) {
    int idx = blockIdx.x * blockDim.x + threadIdx.x;
    int row = idx >> 6;
    int q   = idx & 63;
    if (row >= M) return;
    int seg = __ldg(&g_bidx[row]);
    float4 v = __ldg((const float4*)(g_agg + (size_t)seg * EMB) + q);
    *((float4*)(out + (size_t)row * OUTW + EMB) + q) = v;
}

// ===================== kernel 6 (optional): second tuple output (batch_index) =====================
__global__ void k_tail(float* __restrict__ out, size_t off, int M) {
    int j = blockIdx.x * blockDim.x + threadIdx.x;
    if (j < M) out[off + j] = (float)g_bidx[j];
}

// ===================== launch =====================
extern "C" void kernel_launch(void* const* d_in, const int* in_sizes, int n_in,
                              void* d_out, int out_size) {
    const float* states = (const float*)d_in[0];
    const int*   si     = (const int*)  d_in[1];
    const float* W1     = (const float*)d_in[2];
    const float* b1     = (const float*)d_in[3];
    const float* W2     = (const float*)d_in[4];
    const float* b2     = (const float*)d_in[5];
    float* out = (float*)d_out;

    int M = in_sizes[0] / DEV_DIM;
    int B = in_sizes[1] - 1;
    if (M > MAXM) M = MAXM;
    if (B > MAXB) B = MAXB;

    cudaFuncSetAttribute(k_gemm1_mma, cudaFuncAttributeMaxDynamicSharedMemorySize, SMEM_G1);

    k_init     <<<(B * EMB + 255) / 256, 256>>>(B);
    k_bidx     <<<(M + 255) / 256, 256>>>(si, M, B);
    k_prep     <<<EMB, XDIM>>>(W1);
    k_gemm1_mma<<<(M + 127) / 128, 256, SMEM_G1>>>(states, b1, out, M);
    k_mlp      <<<B, 256>>>(si, W2, b2);
    k_bcast    <<<(M * 64 + 255) / 256, 256>>>(out, M);

    long long need = (long long)M * OUTW + (long long)M;
    if ((long long)out_size >= need)
        k_tail<<<(M + 255) / 256, 256>>>(out, (size_t)M * OUTW, M);
}

// round 11
// speedup vs baseline: 1.1330x; 1.1173x over previous
#include <cuda_runtime.h>
#include <cuda_bf16.h>
#include <math.h>

#define DEV_DIM 192
#define PE_DIM  64
#define EMB     256
#define XDIM    256          // K of GEMM1
#define OUTW    512
#define MAXM    262144
#define MAXB    1024

// ===================== scratch (no allocations allowed) =====================
__device__ float g_sums[MAXB * EMB];
__device__ float g_maxs[MAXB * EMB];
__device__ float g_agg [MAXB * EMB];
__device__ float g_pos [MAXM];
__device__ int   g_bidx[MAXM];
__device__ __nv_bfloat16 g_wt_hi[EMB * XDIM];   // W1^T hi  [n][k]
__device__ __nv_bfloat16 g_wt_lo[EMB * XDIM];   // W1^T lo  [n][k]

// ===================== helpers =====================
__device__ __forceinline__ unsigned smem_u32(const void* p) {
    unsigned a;
    asm("{ .reg .u64 t; cvta.to.shared.u64 t, %1; cvt.u32.u64 %0, t; }" : "=r"(a) : "l"(p));
    return a;
}
__device__ __forceinline__ void cp_async16(unsigned dst, const void* src) {
    asm volatile("cp.async.cg.shared.global [%0], [%1], 16;" :: "r"(dst), "l"(src));
}
#define CP_ASYNC_COMMIT()   asm volatile("cp.async.commit_group;" ::: "memory")
#define CP_ASYNC_WAIT_ALL() asm volatile("cp.async.wait_group 0;" ::: "memory")

#define LDSM_X4(r0, r1, r2, r3, addr)                                          \
    asm volatile("ldmatrix.sync.aligned.m8n8.x4.shared.b16 {%0,%1,%2,%3}, [%4];" \
        : "=r"(r0), "=r"(r1), "=r"(r2), "=r"(r3) : "r"(addr))

__device__ __forceinline__ void mma_bf16(float* d, const unsigned* a, const unsigned* b) {
    asm volatile(
        "mma.sync.aligned.m16n8k16.row.col.f32.bf16.bf16.f32 "
        "{%0,%1,%2,%3}, {%4,%5,%6,%7}, {%8,%9}, {%0,%1,%2,%3};"
        : "+f"(d[0]), "+f"(d[1]), "+f"(d[2]), "+f"(d[3])
        : "r"(a[0]), "r"(a[1]), "r"(a[2]), "r"(a[3]), "r"(b[0]), "r"(b[1]));
}

__device__ __forceinline__ void atomicMaxF(float* addr, float v) {
    if (v >= 0.0f) atomicMax((int*)addr, __float_as_int(v));
    else           atomicMin((unsigned int*)addr, __float_as_uint(v));
}
__device__ __forceinline__ unsigned packbf2(float v0, float v1, float* r0, float* r1) {
    __nv_bfloat16 h0 = __float2bfloat16_rn(v0);
    __nv_bfloat16 h1 = __float2bfloat16_rn(v1);
    *r0 = v0 - __bfloat162float(h0);
    *r1 = v1 - __bfloat162float(h1);
    return ((unsigned)__bfloat16_as_ushort(h1) << 16) | (unsigned)__bfloat16_as_ushort(h0);
}
__device__ __forceinline__ unsigned packbf2_only(float v0, float v1) {
    return ((unsigned)__bfloat16_as_ushort(__float2bfloat16_rn(v1)) << 16)
         | (unsigned)__bfloat16_as_ushort(__float2bfloat16_rn(v0));
}

// ===================== kernel 0: init segment accumulators =====================
__global__ void k_init(int B) {
    int i = blockIdx.x * blockDim.x + threadIdx.x;
    if (i < B * EMB) {
        g_sums[i] = 0.0f;
        ((unsigned int*)g_maxs)[i] = 0xFF800000u;   // -inf
    }
}

// ===================== kernel 1: batch_index + 1-based position =====================
__global__ void k_bidx(const int* __restrict__ si, int M, int B) {
    int j = blockIdx.x * blockDim.x + threadIdx.x;
    if (j >= M) return;
    int lo = 1, hi = B + 1;
    while (lo < hi) {
        int mid = (lo + hi) >> 1;
        if (__ldg(si + mid) <= j) lo = mid + 1; else hi = mid;
    }
    int seg = lo - 1;
    g_bidx[j] = seg;
    g_pos[j]  = (float)(j - __ldg(si + seg) + 1);
}

// ===================== kernel 1b: W1 -> transposed bf16 hi/lo =====================
__global__ void k_prep(const float* __restrict__ W1) {
    int n = blockIdx.x;           // output col 0..255
    int k = threadIdx.x;          // k 0..255
    float w = __ldg(W1 + (size_t)k * EMB + n);
    __nv_bfloat16 h = __float2bfloat16_rn(w);
    g_wt_hi[n * XDIM + k] = h;
    g_wt_lo[n * XDIM + k] = __float2bfloat16_rn(w - __bfloat162float(h));
}

// ===================== kernel 2: bf16x3 HMMA GEMM1 via ldmatrix, 2 CTAs/SM =====================
// CTA: 64 rows x 256 cols (FULL N), 128 threads (4 warps, warp tile 64x64).
// K=256 in 8 chunks of 32, double buffered. Chunks 0-5: states, 6-7: PE.
// 2 resident CTAs per SM overlap each other's sync/wait bubbles.
#define KC       32
#define NCHK     8
#define PA       40                     // smem pitch in bf16 (80 B)
#define A_BUF    5120                   // 64 * 80 B per matrix
#define B_BUF    20480                  // 256 * 80 B per matrix
#define A_TILE   1280                   // 16 * 80 B (one 16-row tile)
#define OFF_BIAS 0                      // 256 f32
#define OFF_INVF 1024                   // 32 f32
#define OFF_A    1280                   // [buf][AH | AL]   2*2*5120  = 20480
#define OFF_B    21760                  // [buf][BH | BL]   2*2*20480 = 81920
#define SMEM_G1  103680

__device__ __forceinline__ void stage_B(unsigned sb, int ck, int buf) {
    int tid = threadIdx.x;
    unsigned bh = sb + OFF_B + buf * (2 * B_BUF);
    unsigned bl = bh + B_BUF;
    const char* srcH = (const char*)(g_wt_hi) + ck * (KC * 2);
    const char* srcL = (const char*)(g_wt_lo) + ck * (KC * 2);
    // per matrix: 256 n-rows * 4 x 16B segments = 1024 txns; 128 threads -> 8 each
#pragma unroll
    for (int t = 0; t < 8; t++) {
        int i = tid + t * 128;
        int n = i >> 2, s = i & 3;
        unsigned d = (unsigned)(n * (PA * 2) + s * 16);
        cp_async16(bh + d, srcH + (size_t)n * (XDIM * 2) + s * 16);
        cp_async16(bl + d, srcL + (size_t)n * (XDIM * 2) + s * 16);
    }
}

__device__ __forceinline__ void load_A_vals(const float* __restrict__ states,
                                            float pos, const float* sinvf,
                                            int grow, int valid, int ck, float* v) {
    int kq = (threadIdx.x & 1) * 16;
    int kbase = ck * KC + kq;
    if (ck < 6) {                       // pure states
        if (valid) {
            const float4* p = (const float4*)(states + (size_t)grow * DEV_DIM + kbase);
#pragma unroll
            for (int q = 0; q < 4; q++) {
                float4 x = __ldg(p + q);
                v[q * 4 + 0] = x.x; v[q * 4 + 1] = x.y;
                v[q * 4 + 2] = x.z; v[q * 4 + 3] = x.w;
            }
        } else {
#pragma unroll
            for (int e = 0; e < 16; e++) v[e] = 0.0f;
        }
    } else {                            // pure PE (k 192..255)
        int c0 = kbase - DEV_DIM;       // 0/16/32/48
#pragma unroll
        for (int f = 0; f < 8; f++) {
            float ang = pos * sinvf[(c0 >> 1) + f];
            float kq2 = rintf(ang * 0.15915494309189535f);
            float rr = fmaf(kq2, -6.28125f, ang);
            rr = fmaf(kq2, -1.9353071795864769e-3f, rr);
            float s, c;
            __sincosf(rr, &s, &c);
            v[2 * f] = s; v[2 * f + 1] = c;
        }
    }
}

__device__ __forceinline__ void store_A(char* smem, int buf, const float* v) {
    int arow = threadIdx.x >> 1;        // 0..63
    int kq   = (threadIdx.x & 1) * 16;
    unsigned hi[8], lo[8];
#pragma unroll
    for (int q = 0; q < 8; q++) {
        float r0, r1;
        hi[q] = packbf2(v[2 * q], v[2 * q + 1], &r0, &r1);
        lo[q] = packbf2_only(r0, r1);
    }
    char* ah = smem + OFF_A + buf * (2 * A_BUF) + arow * (PA * 2) + kq * 2;
    char* al = ah + A_BUF;
    ((uint4*)ah)[0] = make_uint4(hi[0], hi[1], hi[2], hi[3]);
    ((uint4*)ah)[1] = make_uint4(hi[4], hi[5], hi[6], hi[7]);
    ((uint4*)al)[0] = make_uint4(lo[0], lo[1], lo[2], lo[3]);
    ((uint4*)al)[1] = make_uint4(lo[4], lo[5], lo[6], lo[7]);
}

__global__ __launch_bounds__(128, 2) void k_gemm1_mma(
    const float* __restrict__ states, const float* __restrict__ b1,
    float* __restrict__ out, int M)
{
    extern __shared__ char smem[];
    const unsigned sb = smem_u32(smem);
    const int tid  = threadIdx.x;
    const int wid  = tid >> 5;
    const int lane = tid & 31;
    const int g    = lane >> 2;
    const int tg   = lane & 3;
    const int wn   = wid;            // 0..3 (64 cols each); all warps cover rows 0..63
    const int row0 = blockIdx.x * 64;

    float* sbias = (float*)(smem + OFF_BIAS);
    float* sinvf = (float*)(smem + OFF_INVF);

    sbias[tid]       = __ldg(b1 + tid);
    sbias[tid + 128] = __ldg(b1 + tid + 128);
    if (tid < 32) {
        float lg = logf(10000.0f);
        sinvf[tid] = expf(-(lg * ((2.0f * (float)tid) / (float)PE_DIM)));
    }
    __syncthreads();

    const int arow  = tid >> 1;      // 0..63
    const int grow  = row0 + arow;
    const int valid = (grow < M);
    const float pos = valid ? __ldg(&g_pos[grow]) : 1.0f;

    // ldmatrix per-lane base offsets
    const int g4 = lane >> 3;           // 0..3
    const int lr = lane & 7;
    const unsigned a_off = (unsigned)(((g4 & 1) * 8 + lr) * (PA * 2)) + (g4 >> 1) * 16;
    const unsigned b_off = (unsigned)((wn * 64 + (g4 >> 1) * 8 + lr) * (PA * 2)) + (g4 & 1) * 16;

    // ---- prologue: chunk 0 ----
    stage_B(sb, 0, 0);
    CP_ASYNC_COMMIT();
    {
        float v[16];
        load_A_vals(states, pos, sinvf, grow, valid, 0, v);
        store_A(smem, 0, v);
    }
    CP_ASYNC_WAIT_ALL();
    __syncthreads();

    float acc[4][8][4];
#pragma unroll
    for (int i = 0; i < 4; i++)
#pragma unroll
        for (int j = 0; j < 8; j++)
#pragma unroll
            for (int e = 0; e < 4; e++) acc[i][j][e] = 0.0f;

#pragma unroll 1
    for (int c = 0; c < NCHK; c++) {
        const int buf = c & 1;
        float vnext[16];
        const bool more = (c < NCHK - 1);
        if (more) {
            stage_B(sb, c + 1, buf ^ 1);
            CP_ASYNC_COMMIT();
            load_A_vals(states, pos, sinvf, grow, valid, c + 1, vnext);
        }

        const unsigned sAH = sb + OFF_A + buf * (2 * A_BUF);
        const unsigned sAL = sAH + A_BUF;
        const unsigned sBH = sb + OFF_B + buf * (2 * B_BUF);
        const unsigned sBL = sBH + B_BUF;

#pragma unroll
        for (int ks = 0; ks < 2; ks++) {
            const unsigned kb = ks * 32;            // 16 k * 2 B
            unsigned ah[4][4], al[4][4];
#pragma unroll
            for (int i = 0; i < 4; i++) {
                LDSM_X4(ah[i][0], ah[i][1], ah[i][2], ah[i][3],
                        sAH + a_off + i * A_TILE + kb);
                LDSM_X4(al[i][0], al[i][1], al[i][2], al[i][3],
                        sAL + a_off + i * A_TILE + kb);
            }
#pragma unroll
            for (int jj = 0; jj < 4; jj++) {
                unsigned bh[2][2], bl[2][2];
                LDSM_X4(bh[0][0], bh[0][1], bh[1][0], bh[1][1],
                        sBH + b_off + jj * A_TILE + kb);
                LDSM_X4(bl[0][0], bl[0][1], bl[1][0], bl[1][1],
                        sBL + b_off + jj * A_TILE + kb);
#pragma unroll
                for (int i = 0; i < 4; i++) {
#pragma unroll
                    for (int p = 0; p < 2; p++) {
                        mma_bf16(acc[i][2 * jj + p], ah[i], bh[p]);
                        mma_bf16(acc[i][2 * jj + p], ah[i], bl[p]);
                        mma_bf16(acc[i][2 * jj + p], al[i], bh[p]);
                    }
                }
            }
        }

        if (more) {
            store_A(smem, buf ^ 1, vnext);
            CP_ASYNC_WAIT_ALL();
            __syncthreads();
        }
    }

    // ---- epilogue: bias + LeakyReLU, store out[:, 0:256) ----
#pragma unroll
    for (int i = 0; i < 4; i++) {
        int ra = row0 + i * 16 + g;
#pragma unroll
        for (int h = 0; h < 2; h++) {
            int row = ra + h * 8;
            if (row < M) {
                float* op = out + (size_t)row * OUTW + wn * 64;
#pragma unroll
                for (int j = 0; j < 8; j++) {
                    int ccol = j * 8 + tg * 2;
                    float x0 = acc[i][j][h * 2 + 0] + sbias[wn * 64 + ccol];
                    float x1 = acc[i][j][h * 2 + 1] + sbias[wn * 64 + ccol + 1];
                    x0 = (x0 >= 0.0f) ? x0 : 0.01f * x0;
                    x1 = (x1 >= 0.0f) ? x1 : 0.01f * x1;
                    *(float2*)(op + ccol) = make_float2(x0, x1);
                }
            }
        }
    }
}

// ===================== kernel 3: ragged segment sum + max (prefetched) =====================
__global__ __launch_bounds__(256) void k_segred(const float* __restrict__ out, int M) {
    __shared__ int sseg[256];
    int c = threadIdx.x;
    int row0 = blockIdx.x * 256;
    int rows = min(256, M - row0);
    sseg[c] = __ldg(&g_bidx[row0 + min(c, rows - 1)]);
    __syncthreads();
    const float* p = out + (size_t)row0 * OUTW + c;
    float v[8];
#pragma unroll
    for (int i = 0; i < 8; i++)
        v[i] = (i < rows) ? __ldg(p + (size_t)i * OUTW) : 0.0f;
    float sum = 0.0f, mx = __int_as_float(0xFF800000);
    int cur = sseg[0];
#pragma unroll 8
    for (int r = 0; r < 256; r++) {
        if (r >= rows) break;
        float val = v[r & 7];
        if (r + 8 < rows) v[r & 7] = __ldg(p + (size_t)(r + 8) * OUTW);
        int seg = sseg[r];
        if (seg != cur) {
            atomicAdd(&g_sums[cur * EMB + c], sum);
            atomicMaxF(&g_maxs[cur * EMB + c], mx);
            sum = 0.0f; mx = __int_as_float(0xFF800000); cur = seg;
        }
        sum += val;
        mx = fmaxf(mx, val);
    }
    atomicAdd(&g_sums[cur * EMB + c], sum);
    atomicMaxF(&g_maxs[cur * EMB + c], mx);
}

// ===================== kernel 4: agg = leaky(concat(mean,max) @ W2 + b2) =====================
__global__ __launch_bounds__(256) void k_mlp(const int* __restrict__ si,
                                             const float* __restrict__ W2,
                                             const float* __restrict__ b2) {
    __shared__ float vec[2 * EMB];
    __shared__ float par[4][EMB];
    int s = blockIdx.x, t = threadIdx.x;
    int cnt = __ldg(si + s + 1) - __ldg(si + s);
    float inv = (cnt > 0) ? (1.0f / (float)cnt) : 1.0f;
    vec[t]       = g_sums[s * EMB + t] * inv;
    vec[EMB + t] = (cnt > 0) ? g_maxs[s * EMB + t] : 0.0f;
    __syncthreads();
    int tq = t >> 6;
    int tc = (t & 63) * 4;
    float a0 = 0.f, a1 = 0.f, a2 = 0.f, a3 = 0.f;
#pragma unroll 4
    for (int k = tq * 128; k < tq * 128 + 128; k++) {
        float vk = vec[k];
        float4 w = __ldg((const float4*)(W2 + (size_t)k * EMB + tc));
        a0 = fmaf(vk, w.x, a0); a1 = fmaf(vk, w.y, a1);
        a2 = fmaf(vk, w.z, a2); a3 = fmaf(vk, w.w, a3);
    }
    par[tq][tc] = a0; par[tq][tc + 1] = a1; par[tq][tc + 2] = a2; par[tq][tc + 3] = a3;
    __syncthreads();
    if (tq == 0) {
#pragma unroll
        for (int e = 0; e < 4; e++) {
            int cc = tc + e;
            float acc = par[0][cc] + par[1][cc] + par[2][cc] + par[3][cc] + __ldg(b2 + cc);
            acc = (acc >= 0.0f) ? acc : 0.01f * acc;
            g_agg[s * EMB + cc] = acc;
        }
    }
}

// ===================== kernel 5: broadcast agg into out[:, 256:512] =====================
__global__ __launch_bounds__(256) void k_bcast(float* __restrict__ out, int M) {
    int idx = blockIdx.x * blockDim.x + threadIdx.x;
    int row = idx >> 6;
    int q   = idx & 63;
    if (row >= M) return;
    int seg = __ldg(&g_bidx[row]);
    float4 v = __ldg((const float4*)(g_agg + (size_t)seg * EMB) + q);
    *((float4*)(out + (size_t)row * OUTW + EMB) + q) = v;
}

// ===================== kernel 6 (optional): second tuple output (batch_index) =====================
__global__ void k_tail(float* __restrict__ out, size_t off, int M) {
    int j = blockIdx.x * blockDim.x + threadIdx.x;
    if (j < M) out[off + j] = (float)g_bidx[j];
}

// ===================== launch =====================
extern "C" void kernel_launch(void* const* d_in, const int* in_sizes, int n_in,
                              void* d_out, int out_size) {
    const float* states = (const float*)d_in[0];
    const int*   si     = (const int*)  d_in[1];
    const float* W1     = (const float*)d_in[2];
    const float* b1     = (const float*)d_in[3];
    const float* W2     = (const float*)d_in[4];
    const float* b2     = (const float*)d_in[5];
    float* out = (float*)d_out;

    int M = in_sizes[0] / DEV_DIM;
    int B = in_sizes[1] - 1;
    if (M > MAXM) M = MAXM;
    if (B > MAXB) B = MAXB;

    cudaFuncSetAttribute(k_gemm1_mma, cudaFuncAttributeMaxDynamicSharedMemorySize, SMEM_G1);

    k_init     <<<(B * EMB + 255) / 256, 256>>>(B);
    k_bidx     <<<(M + 255) / 256, 256>>>(si, M, B);
    k_prep     <<<EMB, XDIM>>>(W1);
    k_gemm1_mma<<<(M + 63) / 64, 128, SMEM_G1>>>(states, b1, out, M);
    k_segred   <<<(M + 255) / 256, 256>>>(out, M);
    k_mlp      <<<B, 256>>>(si, W2, b2);
    k_bcast    <<<(M * 64 + 255) / 256, 256>>>(out, M);

    long long need = (long long)M * OUTW + (long long)M;
    if ((long long)out_size >= need)
        k_tail<<<(M + 255) / 256, 256>>>(out, (size_t)M * OUTW, M);
}

// round 12
// speedup vs baseline: 1.1684x; 1.0312x over previous
#include <cuda_runtime.h>
#include <cuda_bf16.h>
#include <math.h>

#define DEV_DIM 192
#define PE_DIM  64
#define EMB     256
#define XDIM    256          // K of GEMM1
#define OUTW    512
#define MAXM    262144
#define MAXB    1024

// ===================== scratch (no allocations allowed) =====================
__device__ float g_sums[MAXB * EMB];
__device__ float g_maxs[MAXB * EMB];
__device__ float g_agg [MAXB * EMB];
__device__ float g_pos [MAXM];
__device__ int   g_bidx[MAXM];
__device__ __nv_bfloat16 g_wt_hi[EMB * XDIM];   // W1^T hi  [n][k]
__device__ __nv_bfloat16 g_wt_lo[EMB * XDIM];   // W1^T lo  [n][k]

// ===================== helpers =====================
__device__ __forceinline__ unsigned smem_u32(const void* p) {
    unsigned a;
    asm("{ .reg .u64 t; cvta.to.shared.u64 t, %1; cvt.u32.u64 %0, t; }" : "=r"(a) : "l"(p));
    return a;
}
__device__ __forceinline__ void cp_async16(unsigned dst, const void* src) {
    asm volatile("cp.async.cg.shared.global [%0], [%1], 16;" :: "r"(dst), "l"(src));
}
#define CP_ASYNC_COMMIT()   asm volatile("cp.async.commit_group;" ::: "memory")
#define CP_ASYNC_WAIT_ALL() asm volatile("cp.async.wait_group 0;" ::: "memory")

#define LDSM_X4(r0, r1, r2, r3, addr)                                          \
    asm volatile("ldmatrix.sync.aligned.m8n8.x4.shared.b16 {%0,%1,%2,%3}, [%4];" \
        : "=r"(r0), "=r"(r1), "=r"(r2), "=r"(r3) : "r"(addr))

__device__ __forceinline__ void mma_bf16(float* d, const unsigned* a, const unsigned* b) {
    asm volatile(
        "mma.sync.aligned.m16n8k16.row.col.f32.bf16.bf16.f32 "
        "{%0,%1,%2,%3}, {%4,%5,%6,%7}, {%8,%9}, {%0,%1,%2,%3};"
        : "+f"(d[0]), "+f"(d[1]), "+f"(d[2]), "+f"(d[3])
        : "r"(a[0]), "r"(a[1]), "r"(a[2]), "r"(a[3]), "r"(b[0]), "r"(b[1]));
}

__device__ __forceinline__ void atomicMaxF(float* addr, float v) {
    if (v >= 0.0f) atomicMax((int*)addr, __float_as_int(v));
    else           atomicMin((unsigned int*)addr, __float_as_uint(v));
}
__device__ __forceinline__ unsigned packbf2(float v0, float v1, float* r0, float* r1) {
    __nv_bfloat16 h0 = __float2bfloat16_rn(v0);
    __nv_bfloat16 h1 = __float2bfloat16_rn(v1);
    *r0 = v0 - __bfloat162float(h0);
    *r1 = v1 - __bfloat162float(h1);
    return ((unsigned)__bfloat16_as_ushort(h1) << 16) | (unsigned)__bfloat16_as_ushort(h0);
}
__device__ __forceinline__ unsigned packbf2_only(float v0, float v1) {
    return ((unsigned)__bfloat16_as_ushort(__float2bfloat16_rn(v1)) << 16)
         | (unsigned)__bfloat16_as_ushort(__float2bfloat16_rn(v0));
}

// ===================== kernel 0: init segment accumulators =====================
__global__ void k_init(int B) {
    int i = blockIdx.x * blockDim.x + threadIdx.x;
    if (i < B * EMB) {
        g_sums[i] = 0.0f;
        ((unsigned int*)g_maxs)[i] = 0xFF800000u;   // -inf
    }
}

// ===================== kernel 1: batch_index + 1-based position =====================
__global__ void k_bidx(const int* __restrict__ si, int M, int B) {
    int j = blockIdx.x * blockDim.x + threadIdx.x;
    if (j >= M) return;
    int lo = 1, hi = B + 1;
    while (lo < hi) {
        int mid = (lo + hi) >> 1;
        if (__ldg(si + mid) <= j) lo = mid + 1; else hi = mid;
    }
    int seg = lo - 1;
    g_bidx[j] = seg;
    g_pos[j]  = (float)(j - __ldg(si + seg) + 1);
}

// ===================== kernel 1b: W1 -> transposed bf16 hi/lo =====================
__global__ void k_prep(const float* __restrict__ W1) {
    int n = blockIdx.x;           // output col 0..255
    int k = threadIdx.x;          // k 0..255
    float w = __ldg(W1 + (size_t)k * EMB + n);
    __nv_bfloat16 h = __float2bfloat16_rn(w);
    g_wt_hi[n * XDIM + k] = h;
    g_wt_lo[n * XDIM + k] = __float2bfloat16_rn(w - __bfloat162float(h));
}

// ===================== kernel 2: bf16x3 HMMA GEMM1 via ldmatrix, 2 CTAs/SM =====================
// CTA: 64 rows x 256 cols (FULL N), 256 threads (8 warps, warp tile 32x64).
// K=256 in 8 chunks of 32, double buffered. Chunks 0-5: states, 6-7: PE.
// 2 resident CTAs per SM (16 warps) overlap sync/wait bubbles.
#define KC       32
#define NCHK     8
#define PA       40                     // smem pitch in bf16 (80 B)
#define A_BUF    5120                   // 64 * 80 B per matrix
#define B_BUF    20480                  // 256 * 80 B per matrix
#define A_TILE   1280                   // 16 * 80 B (one 16-row tile)
#define OFF_BIAS 0                      // 256 f32
#define OFF_INVF 1024                   // 32 f32
#define OFF_A    1280                   // [buf][AH | AL]   2*2*5120  = 20480
#define OFF_B    21760                  // [buf][BH | BL]   2*2*20480 = 81920
#define SMEM_G1  103680

__device__ __forceinline__ void stage_B(unsigned sb, int ck, int buf) {
    int tid = threadIdx.x;
    unsigned bh = sb + OFF_B + buf * (2 * B_BUF);
    unsigned bl = bh + B_BUF;
    const char* srcH = (const char*)(g_wt_hi) + ck * (KC * 2);
    const char* srcL = (const char*)(g_wt_lo) + ck * (KC * 2);
    // per matrix: 256 n-rows * 4 x 16B segments = 1024 txns; 256 threads -> 4 each
#pragma unroll
    for (int t = 0; t < 4; t++) {
        int i = tid + t * 256;
        int n = i >> 2, s = i & 3;
        unsigned d = (unsigned)(n * (PA * 2) + s * 16);
        cp_async16(bh + d, srcH + (size_t)n * (XDIM * 2) + s * 16);
        cp_async16(bl + d, srcL + (size_t)n * (XDIM * 2) + s * 16);
    }
}

// Each thread handles 8 consecutive k of one row: arow = tid>>2, kq = (tid&3)*8.
__device__ __forceinline__ void load_A_vals(const float* __restrict__ states,
                                            float pos, const float* sinvf,
                                            int grow, int valid, int ck, float* v) {
    int kq = (threadIdx.x & 3) * 8;
    int kbase = ck * KC + kq;
    if (ck < 6) {                       // pure states
        if (valid) {
            const float4* p = (const float4*)(states + (size_t)grow * DEV_DIM + kbase);
            float4 x = __ldg(p);
            float4 y = __ldg(p + 1);
            v[0] = x.x; v[1] = x.y; v[2] = x.z; v[3] = x.w;
            v[4] = y.x; v[5] = y.y; v[6] = y.z; v[7] = y.w;
        } else {
#pragma unroll
            for (int e = 0; e < 8; e++) v[e] = 0.0f;
        }
    } else {                            // pure PE (k 192..255)
        int c0 = kbase - DEV_DIM;       // multiple of 8
#pragma unroll
        for (int f = 0; f < 4; f++) {
            float ang = pos * sinvf[(c0 >> 1) + f];
            float kq2 = rintf(ang * 0.15915494309189535f);
            float rr = fmaf(kq2, -6.28125f, ang);
            rr = fmaf(kq2, -1.9353071795864769e-3f, rr);
            float s, c;
            __sincosf(rr, &s, &c);
            v[2 * f] = s; v[2 * f + 1] = c;
        }
    }
}

__device__ __forceinline__ void store_A(char* smem, int buf, const float* v) {
    int arow = threadIdx.x >> 2;        // 0..63
    int kq   = (threadIdx.x & 3) * 8;
    unsigned hi[4], lo[4];
#pragma unroll
    for (int q = 0; q < 4; q++) {
        float r0, r1;
        hi[q] = packbf2(v[2 * q], v[2 * q + 1], &r0, &r1);
        lo[q] = packbf2_only(r0, r1);
    }
    char* ah = smem + OFF_A + buf * (2 * A_BUF) + arow * (PA * 2) + kq * 2;
    char* al = ah + A_BUF;
    *(uint4*)ah = make_uint4(hi[0], hi[1], hi[2], hi[3]);
    *(uint4*)al = make_uint4(lo[0], lo[1], lo[2], lo[3]);
}

__global__ __launch_bounds__(256, 2) void k_gemm1_mma(
    const float* __restrict__ states, const float* __restrict__ b1,
    float* __restrict__ out, int M)
{
    extern __shared__ char smem[];
    const unsigned sb = smem_u32(smem);
    const int tid  = threadIdx.x;
    const int wid  = tid >> 5;
    const int lane = tid & 31;
    const int g    = lane >> 2;
    const int tg   = lane & 3;
    const int wm   = wid >> 2;       // 0..1 (32 rows each)
    const int wn   = wid & 3;        // 0..3 (64 cols each)
    const int row0 = blockIdx.x * 64;

    float* sbias = (float*)(smem + OFF_BIAS);
    float* sinvf = (float*)(smem + OFF_INVF);

    sbias[tid] = __ldg(b1 + tid);
    if (tid < 32) {
        float lg = logf(10000.0f);
        sinvf[tid] = expf(-(lg * ((2.0f * (float)tid) / (float)PE_DIM)));
    }
    __syncthreads();

    const int arow  = tid >> 2;      // 0..63
    const int grow  = row0 + arow;
    const int valid = (grow < M);
    const float pos = valid ? __ldg(&g_pos[grow]) : 1.0f;

    // ldmatrix per-lane base offsets
    const int g4 = lane >> 3;           // 0..3
    const int lr = lane & 7;
    const unsigned a_off = (unsigned)((wm * 32 + (g4 & 1) * 8 + lr) * (PA * 2)) + (g4 >> 1) * 16;
    const unsigned b_off = (unsigned)((wn * 64 + (g4 >> 1) * 8 + lr) * (PA * 2)) + (g4 & 1) * 16;

    // ---- prologue: chunk 0 ----
    stage_B(sb, 0, 0);
    CP_ASYNC_COMMIT();
    {
        float v[8];
        load_A_vals(states, pos, sinvf, grow, valid, 0, v);
        store_A(smem, 0, v);
    }
    CP_ASYNC_WAIT_ALL();
    __syncthreads();

    float acc[2][8][4];
#pragma unroll
    for (int i = 0; i < 2; i++)
#pragma unroll
        for (int j = 0; j < 8; j++)
#pragma unroll
            for (int e = 0; e < 4; e++) acc[i][j][e] = 0.0f;

#pragma unroll 1
    for (int c = 0; c < NCHK; c++) {
        const int buf = c & 1;
        float vnext[8];
        const bool more = (c < NCHK - 1);
        if (more) {
            stage_B(sb, c + 1, buf ^ 1);
            CP_ASYNC_COMMIT();
            load_A_vals(states, pos, sinvf, grow, valid, c + 1, vnext);
        }

        const unsigned sAH = sb + OFF_A + buf * (2 * A_BUF);
        const unsigned sAL = sAH + A_BUF;
        const unsigned sBH = sb + OFF_B + buf * (2 * B_BUF);
        const unsigned sBL = sBH + B_BUF;

#pragma unroll
        for (int ks = 0; ks < 2; ks++) {
            const unsigned kb = ks * 32;            // 16 k * 2 B
            unsigned ah[2][4], al[2][4];
#pragma unroll
            for (int i = 0; i < 2; i++) {
                LDSM_X4(ah[i][0], ah[i][1], ah[i][2], ah[i][3],
                        sAH + a_off + i * A_TILE + kb);
                LDSM_X4(al[i][0], al[i][1], al[i][2], al[i][3],
                        sAL + a_off + i * A_TILE + kb);
            }
#pragma unroll
            for (int jj = 0; jj < 4; jj++) {
                unsigned bh[2][2], bl[2][2];
                LDSM_X4(bh[0][0], bh[0][1], bh[1][0], bh[1][1],
                        sBH + b_off + jj * A_TILE + kb);
                LDSM_X4(bl[0][0], bl[0][1], bl[1][0], bl[1][1],
                        sBL + b_off + jj * A_TILE + kb);
#pragma unroll
                for (int i = 0; i < 2; i++) {
#pragma unroll
                    for (int p = 0; p < 2; p++) {
                        mma_bf16(acc[i][2 * jj + p], ah[i], bh[p]);
                        mma_bf16(acc[i][2 * jj + p], ah[i], bl[p]);
                        mma_bf16(acc[i][2 * jj + p], al[i], bh[p]);
                    }
                }
            }
        }

        if (more) {
            store_A(smem, buf ^ 1, vnext);
            CP_ASYNC_WAIT_ALL();
            __syncthreads();
        }
    }

    // ---- epilogue: bias + LeakyReLU, store out[:, 0:256) ----
#pragma unroll
    for (int i = 0; i < 2; i++) {
        int ra = row0 + wm * 32 + i * 16 + g;
#pragma unroll
        for (int h = 0; h < 2; h++) {
            int row = ra + h * 8;
            if (row < M) {
                float* op = out + (size_t)row * OUTW + wn * 64;
#pragma unroll
                for (int j = 0; j < 8; j++) {
                    int ccol = j * 8 + tg * 2;
                    float x0 = acc[i][j][h * 2 + 0] + sbias[wn * 64 + ccol];
                    float x1 = acc[i][j][h * 2 + 1] + sbias[wn * 64 + ccol + 1];
                    x0 = (x0 >= 0.0f) ? x0 : 0.01f * x0;
                    x1 = (x1 >= 0.0f) ? x1 : 0.01f * x1;
                    *(float2*)(op + ccol) = make_float2(x0, x1);
                }
            }
        }
    }
}

// ===================== kernel 3: ragged segment sum + max (prefetched) =====================
__global__ __launch_bounds__(256) void k_segred(const float* __restrict__ out, int M) {
    __shared__ int sseg[256];
    int c = threadIdx.x;
    int row0 = blockIdx.x * 256;
    int rows = min(256, M - row0);
    sseg[c] = __ldg(&g_bidx[row0 + min(c, rows - 1)]);
    __syncthreads();
    const float* p = out + (size_t)row0 * OUTW + c;
    float v[8];
#pragma unroll
    for (int i = 0; i < 8; i++)
        v[i] = (i < rows) ? __ldg(p + (size_t)i * OUTW) : 0.0f;
    float sum = 0.0f, mx = __int_as_float(0xFF800000);
    int cur = sseg[0];
#pragma unroll 8
    for (int r = 0; r < 256; r++) {
        if (r >= rows) break;
        float val = v[r & 7];
        if (r + 8 < rows) v[r & 7] = __ldg(p + (size_t)(r + 8) * OUTW);
        int seg = sseg[r];
        if (seg != cur) {
            atomicAdd(&g_sums[cur * EMB + c], sum);
            atomicMaxF(&g_maxs[cur * EMB + c], mx);
            sum = 0.0f; mx = __int_as_float(0xFF800000); cur = seg;
        }
        sum += val;
        mx = fmaxf(mx, val);
    }
    atomicAdd(&g_sums[cur * EMB + c], sum);
    atomicMaxF(&g_maxs[cur * EMB + c], mx);
}

// ===================== kernel 4: agg = leaky(concat(mean,max) @ W2 + b2) =====================
__global__ __launch_bounds__(256) void k_mlp(const int* __restrict__ si,
                                             const float* __restrict__ W2,
                                             const float* __restrict__ b2) {
    __shared__ float vec[2 * EMB];
    __shared__ float par[4][EMB];
    int s = blockIdx.x, t = threadIdx.x;
    int cnt = __ldg(si + s + 1) - __ldg(si + s);
    float inv = (cnt > 0) ? (1.0f / (float)cnt) : 1.0f;
    vec[t]       = g_sums[s * EMB + t] * inv;
    vec[EMB + t] = (cnt > 0) ? g_maxs[s * EMB + t] : 0.0f;
    __syncthreads();
    int tq = t >> 6;
    int tc = (t & 63) * 4;
    float a0 = 0.f, a1 = 0.f, a2 = 0.f, a3 = 0.f;
#pragma unroll 4
    for (int k = tq * 128; k < tq * 128 + 128; k++) {
        float vk = vec[k];
        float4 w = __ldg((const float4*)(W2 + (size_t)k * EMB + tc));
        a0 = fmaf(vk, w.x, a0); a1 = fmaf(vk, w.y, a1);
        a2 = fmaf(vk, w.z, a2); a3 = fmaf(vk, w.w, a3);
    }
    par[tq][tc] = a0; par[tq][tc + 1] = a1; par[tq][tc + 2] = a2; par[tq][tc + 3] = a3;
    __syncthreads();
    if (tq == 0) {
#pragma unroll
        for (int e = 0; e < 4; e++) {
            int cc = tc + e;
            float acc = par[0][cc] + par[1][cc] + par[2][cc] + par[3][cc] + __ldg(b2 + cc);
            acc = (acc >= 0.0f) ? acc : 0.01f * acc;
            g_agg[s * EMB + cc] = acc;
        }
    }
}

// ===================== kernel 5: broadcast agg into out[:, 256:512] =====================
__global__ __launch_bounds__(256) void k_bcast(float* __restrict__ out, int M) {
    int idx = blockIdx.x * blockDim.x + threadIdx.x;
    int row = idx >> 6;
    int q   = idx & 63;
    if (row >= M) return;
    int seg = __ldg(&g_bidx[row]);
    float4 v = __ldg((const float4*)(g_agg + (size_t)seg * EMB) + q);
    *((float4*)(out + (size_t)row * OUTW + EMB) + q) = v;
}

// ===================== kernel 6 (optional): second tuple output (batch_index) =====================
__global__ void k_tail(float* __restrict__ out, size_t off, int M) {
    int j = blockIdx.x * blockDim.x + threadIdx.x;
    if (j < M) out[off + j] = (float)g_bidx[j];
}

// ===================== launch =====================
extern "C" void kernel_launch(void* const* d_in, const int* in_sizes, int n_in,
                              void* d_out, int out_size) {
    const float* states = (const float*)d_in[0];
    const int*   si     = (const int*)  d_in[1];
    const float* W1     = (const float*)d_in[2];
    const float* b1     = (const float*)d_in[3];
    const float* W2     = (const float*)d_in[4];
    const float* b2     = (const float*)d_in[5];
    float* out = (float*)d_out;

    int M = in_sizes[0] / DEV_DIM;
    int B = in_sizes[1] - 1;
    if (M > MAXM) M = MAXM;
    if (B > MAXB) B = MAXB;

    cudaFuncSetAttribute(k_gemm1_mma, cudaFuncAttributeMaxDynamicSharedMemorySize, SMEM_G1);

    k_init     <<<(B * EMB + 255) / 256, 256>>>(B);
    k_bidx     <<<(M + 255) / 256, 256>>>(si, M, B);
    k_prep     <<<EMB, XDIM>>>(W1);
    k_gemm1_mma<<<(M + 63) / 64, 256, SMEM_G1>>>(states, b1, out, M);
    k_segred   <<<(M + 255) / 256, 256>>>(out, M);
    k_mlp      <<<B, 256>>>(si, W2, b2);
    k_bcast    <<<(M * 64 + 255) / 256, 256>>>(out, M);

    long long need = (long long)M * OUTW + (long long)M;
    if ((long long)out_size >= need)
        k_tail<<<(M + 255) / 256, 256>>>(out, (size_t)M * OUTW, M);
}